// round 16
// baseline (speedup 1.0000x reference)
#include <cuda_runtime.h>

#define HW      256
#define NB      8
#define CH      64
#define HWHW    65536
#define F4ROW   64        // HW/4
#define F4IMG   16384     // HWHW/4
#define THREADS 512

__device__ __forceinline__ void acc_abs(float4& s, const float4 a) {
    s.x += fabsf(a.x); s.y += fabsf(a.y); s.z += fabsf(a.z); s.w += fabsf(a.w);
}

// reduce float4 over aligned 4-lane groups (lane bits 0..1)
__device__ __forceinline__ void red4(float4& s) {
    s.x += __shfl_xor_sync(0xffffffffu, s.x, 1, 4);
    s.y += __shfl_xor_sync(0xffffffffu, s.y, 1, 4);
    s.z += __shfl_xor_sync(0xffffffffu, s.z, 1, 4);
    s.w += __shfl_xor_sync(0xffffffffu, s.w, 1, 4);
    s.x += __shfl_xor_sync(0xffffffffu, s.x, 2, 4);
    s.y += __shfl_xor_sync(0xffffffffu, s.y, 2, 4);
    s.z += __shfl_xor_sync(0xffffffffu, s.z, 2, 4);
    s.w += __shfl_xor_sync(0xffffffffu, s.w, 2, 4);
}

__global__ void __launch_bounds__(THREADS, 3)
k_fused(const float* __restrict__ x1, const float* __restrict__ x2,
        const float* __restrict__ w,  const float* __restrict__ bias,
        float* __restrict__ out) {
    __shared__ float nrm[3][2][HW];      // rows r-1, r, r+1  x  {n1, n2}
    __shared__ float f1s[HW], f2s[HW];

    const int u  = blockIdx.x;           // 0..2047
    const int bb = u >> 8;               // batch
    const int r  = u & 255;              // row
    const int t  = threadIdx.x;
    const int arr  = t >> 8;             // 0: x1, 1: x2
    const int grp  = t & 3;              // 16-channel group (lane bits 0..1)
    const int quad = (t >> 2) & 63;      // float4 quad (pixels 4q..4q+3)

    const size_t imgf4 = (size_t)bb * CH * F4IMG;
    const float4* px = (const float4*)(arr ? x2 : x1) + imgf4
                     + (size_t)(grp * 16) * F4IMG + quad;

    // ---- pass A: halo rows r-1 and r+1 (2 accumulators) ----
    {
        const bool vA = (r > 0), vB = (r < HW - 1);
        const float4* pA = px + (size_t)(vA ? r - 1 : 0) * F4ROW;
        const float4* pB = px + (size_t)(vB ? r + 1 : 0) * F4ROW;
        float4 aA = make_float4(0.f, 0.f, 0.f, 0.f);
        float4 aB = make_float4(0.f, 0.f, 0.f, 0.f);
#pragma unroll
        for (int j = 0; j < 16; ++j) {
            if (vA) acc_abs(aA, pA[(size_t)j * F4IMG]);
            if (vB) acc_abs(aB, pB[(size_t)j * F4IMG]);
        }
        red4(aA);
        red4(aB);
        if (grp == 0) {                  // zero for OOR rows == zero-pad
            ((float4*)nrm[0][arr])[quad] = aA;
            ((float4*)nrm[2][arr])[quad] = aB;
        }
    }

    // ---- pass B: own row r last (stays L1-hot for the blend) ----
    {
        const float4* pC = px + (size_t)r * F4ROW;
        float4 aC = make_float4(0.f, 0.f, 0.f, 0.f);
#pragma unroll
        for (int j = 0; j < 16; ++j)
            acc_abs(aC, pC[(size_t)j * F4IMG]);
        red4(aC);
        if (grp == 0)
            ((float4*)nrm[1][arr])[quad] = aC;
    }
    __syncthreads();

    // ---- 3x3 conv factors for the 256 pixels of row r ----
    if (t < HW) {
        float c1 = __ldg(bias), c2 = c1;
#pragma unroll
        for (int dr = 0; dr < 3; ++dr) {
            const float* n1r = nrm[dr][0];
            const float* n2r = nrm[dr][1];
#pragma unroll
            for (int dj = 0; dj < 3; ++dj) {
                const int cc = t + dj - 1;
                if (cc < 0 || cc >= HW) continue;
                const float ww = __ldg(w + dr * 3 + dj);
                c1 += ww * n1r[cc];
                c2 += ww * n2r[cc];
            }
        }
        const float rd = 1.0f / (c1 + c2);
        f1s[t] = c1 * rd;
        f2s[t] = c2 * rd;
    }
    __syncthreads();

    // ---- blend: re-read row r (L1/L2 hit), streaming store ----
    const int chb = t >> 6;              // base channel 0..7
    const int qq  = t & 63;
    const size_t base = imgf4 + (size_t)chb * F4IMG + (size_t)r * F4ROW + qq;
    const float4* p1 = (const float4*)x1 + base;
    const float4* p2 = (const float4*)x2 + base;
    float4*       po = (float4*)out + base;
    const float4 F1 = ((const float4*)f1s)[qq];
    const float4 F2 = ((const float4*)f2s)[qq];
#pragma unroll
    for (int i = 0; i < 8; ++i) {        // channels chb, chb+8, ..., chb+56
        const size_t off = (size_t)i * 8 * F4IMG;
        const float4 a = __ldcs(p1 + off);
        const float4 v = __ldcs(p2 + off);
        float4 o;
        o.x = a.x * F1.x + v.x * F2.x;
        o.y = a.y * F1.y + v.y * F2.y;
        o.z = a.z * F1.z + v.z * F2.z;
        o.w = a.w * F1.w + v.w * F2.w;
        __stcs(po + off, o);
    }
}

extern "C" void kernel_launch(void* const* d_in, const int* in_sizes, int n_in,
                              void* d_out, int out_size) {
    const float* x1   = (const float*)d_in[0];
    const float* x2   = (const float*)d_in[1];
    const float* w    = (const float*)d_in[2];
    const float* bias = (const float*)d_in[3];
    float*       out  = (float*)d_out;

    k_fused<<<NB * HW, THREADS>>>(x1, x2, w, bias, out);
}